// round 14
// baseline (speedup 1.0000x reference)
#include <cuda_runtime.h>

#define Bsz 128
#define Hdim 256
#define Wdim 1024
#define N_HOLES 5
#define PROB 1.0f
#define HOLE_MINW (Wdim / 10)              // 102
#define HOLE_MINH (Hdim / 10)              // 25
#define N_TOTAL ((long long)Bsz * Hdim * Wdim)   // 33,554,432 floats
#define NHOLE_T (Bsz * N_HOLES)            // 640

#define GRID 592                           // 148 SMs * 4 -> balanced residency
#define NT 256
#define JB 8                               // batched LDG.128 per tile
#define TILE (NT * JB)                     // 2048 float4 = 32 KB contiguous
#define NTILES ((int)(N_TOTAL / 4 / TILE)) // 4096 exactly

__device__ float g_partials[GRID];
__device__ float g_mean;
__device__ int   g_count = 0;              // last block resets -> replay-safe
__device__ int   g_epoch = 0;              // monotonic: bumps once per launch

// Fused kernel, contiguous-tile copy phase (DRAM row locality):
//  phase 1: grid-stride over 32KB tiles; inside a tile, 8 front-batched
//           LDG.128 4KB apart -> fully contiguous request stream per block
//  sync:    ticket counter; last block reduces partials -> g_mean, bumps epoch
//  phase 2: all blocks stride the 640 holes, vectorized rect fill
__global__ void __launch_bounds__(NT, 4) fused_cutout_kernel(
    const float4* __restrict__ x, float4* __restrict__ out,
    const int* __restrict__ xs, const int* __restrict__ ys,
    const int* __restrict__ xs_w_raw, const int* __restrict__ ys_h_raw,
    const float* __restrict__ act_rand)
{
    // Read epoch before any block could possibly bump it (bump requires all
    // GRID tickets; ours comes later).
    const int epoch0 = *(volatile int*)&g_epoch;

    // ---- phase 1: copy + reduce over contiguous 32KB tiles ----
    float s = 0.0f;
    #pragma unroll 1
    for (int t = blockIdx.x; t < NTILES; t += GRID) {
        const long long base = (long long)t * TILE + threadIdx.x;
        float4 v[JB];
        #pragma unroll
        for (int j = 0; j < JB; ++j)
            v[j] = x[base + j * NT];
        #pragma unroll
        for (int j = 0; j < JB; ++j) {
            s += (v[j].x + v[j].y) + (v[j].z + v[j].w);
            out[base + j * NT] = v[j];
        }
    }

    #pragma unroll
    for (int o = 16; o > 0; o >>= 1)
        s += __shfl_down_sync(0xFFFFFFFFu, s, o);
    __shared__ float ws[8];
    const int lane = threadIdx.x & 31, warp = threadIdx.x >> 5;
    if (lane == 0) ws[warp] = s;
    __syncthreads();
    __shared__ int is_last;
    if (threadIdx.x == 0) {
        float v = ws[0];
        #pragma unroll
        for (int k = 1; k < 8; ++k) v += ws[k];
        g_partials[blockIdx.x] = v;
        __threadfence();
        int ticket = atomicAdd(&g_count, 1);
        is_last = (ticket == GRID - 1);
    }
    __syncthreads();

    if (is_last) {
        // fixed-order float reduction of GRID partials (deterministic)
        float s2 = 0.0f;
        for (int k = threadIdx.x; k < GRID; k += NT)
            s2 += g_partials[k];
        #pragma unroll
        for (int o = 16; o > 0; o >>= 1)
            s2 += __shfl_down_sync(0xFFFFFFFFu, s2, o);
        __shared__ float wf[8];
        if (lane == 0) wf[warp] = s2;
        __syncthreads();
        if (threadIdx.x == 0) {
            float t = wf[0];
            #pragma unroll
            for (int k = 1; k < 8; ++k) t += wf[k];
            g_mean = t * (1.0f / (float)N_TOTAL);
            g_count = 0;                   // reset for next replay
            __threadfence();
            *(volatile int*)&g_epoch = epoch0 + 1;   // release
        }
    }

    // ---- grid-wide sync: thread 0 spins, block follows ----
    if (threadIdx.x == 0) {
        while (*(volatile int*)&g_epoch == epoch0)
            __nanosleep(32);
    }
    __syncthreads();
    __threadfence();                       // acquire
    const float fill = *(volatile float*)&g_mean;
    const float4 f4 = make_float4(fill, fill, fill, fill);

    // ---- phase 2: fill holes (all blocks, strided) ----
    const int qx = threadIdx.x & 63;       // quad lane
    const int ry = threadIdx.x >> 6;       // row lane (0..3)

    for (int hole = blockIdx.x; hole < NHOLE_T; hole += GRID) {
        if (!(act_rand[hole] < PROB)) continue;
        const int b = hole / N_HOLES;

        const int hw = xs_w_raw[hole] + HOLE_MINW;
        const int hh = ys_h_raw[hole] + HOLE_MINH;
        const int cw = xs[hole], ch = ys[hole];
        const int x0 = min(max(cw - hw / 2, 0), Wdim - 2);
        const int x1 = min(max(cw + hw / 2, 1), Wdim - 1);
        const int y0 = min(max(ch - hh / 2, 0), Hdim - 2);
        const int y1 = min(max(ch + hh / 2, 1), Hdim - 1);

        const int a0 = (x0 + 3) & ~3;      // first aligned float index
        const int a1 = (x1 + 1) & ~3;      // exclusive aligned end
        const int nvec = (a1 - a0) >> 2;   // float4 interior count

        const int wl = x0 + qx;            // left-edge scalar (qx < 3)
        const bool do_l = (qx < 3) && (wl < a0);
        const int wr = a1 + (qx - 3);      // right-edge scalar (qx in [3,6))
        const bool do_r = (qx >= 3) && (qx < 6) && (wr <= x1);

        float* const base = (float*)out + (size_t)b * Hdim * Wdim + a0;
        for (int h = y0 + ry; h <= y1; h += 4) {
            float* const row = base + (size_t)h * Wdim;
            if (do_l) row[wl - a0] = fill;
            if (do_r) row[wr - a0] = fill;
            float4* const rowv = reinterpret_cast<float4*>(row);
            for (int q = qx; q < nvec; q += 64)
                rowv[q] = f4;
        }
    }
}

extern "C" void kernel_launch(void* const* d_in, const int* in_sizes, int n_in,
                              void* d_out, int out_size) {
    const float* x        = (const float*)d_in[0];
    const int*   xs       = (const int*)d_in[1];
    const int*   ys       = (const int*)d_in[2];
    const int*   xs_w_raw = (const int*)d_in[3];
    const int*   ys_h_raw = (const int*)d_in[4];
    const float* act_rand = (const float*)d_in[5];
    float* out = (float*)d_out;

    fused_cutout_kernel<<<GRID, NT>>>((const float4*)x, (float4*)out,
                                      xs, ys, xs_w_raw, ys_h_raw, act_rand);
}

// round 15
// speedup vs baseline: 1.0028x; 1.0028x over previous
#include <cuda_runtime.h>

#define Bsz 128
#define Hdim 256
#define Wdim 1024
#define N_HOLES 5
#define PROB 1.0f
#define HOLE_MINW (Wdim / 10)              // 102
#define HOLE_MINH (Hdim / 10)              // 25
#define N_TOTAL ((long long)Bsz * Hdim * Wdim)   // 33,554,432 floats
#define NHOLE_T (Bsz * N_HOLES)            // 640

#define GRID 592                           // 148 SMs * 4 -> perfectly balanced
#define NT 256
#define TOTT (GRID * NT)                   // 151,552 threads
#define N4 (N_TOTAL / 4)                   // 8,388,608 float4

__device__ float g_partials[GRID];
__device__ float g_mean;
__device__ int   g_count = 0;              // last block resets -> replay-safe
__device__ int   g_epoch = 0;              // monotonic: bumps once per launch

struct Rect { int x0, x1, y0, y1, b; };

// Clamp + activation; inactive -> empty rect (y1 < y0)
__device__ __forceinline__ Rect load_rect(
    int hole, const int* __restrict__ xs, const int* __restrict__ ys,
    const int* __restrict__ xs_w_raw, const int* __restrict__ ys_h_raw,
    const float* __restrict__ act_rand)
{
    Rect r; r.y0 = 0; r.y1 = -1; r.x0 = 0; r.x1 = 0; r.b = 0;
    if (hole < NHOLE_T && act_rand[hole] < PROB) {
        r.b = hole / N_HOLES;
        const int hw = xs_w_raw[hole] + HOLE_MINW;
        const int hh = ys_h_raw[hole] + HOLE_MINH;
        const int cw = xs[hole], ch = ys[hole];
        r.x0 = min(max(cw - hw / 2, 0), Wdim - 2);
        r.x1 = min(max(cw + hw / 2, 1), Wdim - 1);
        r.y0 = min(max(ch - hh / 2, 0), Hdim - 2);
        r.y1 = min(max(ch + hh / 2, 1), Hdim - 1);
    }
    return r;
}

__device__ __forceinline__ void fill_rect(const Rect& r, float fill,
                                          float* __restrict__ out,
                                          int qx, int ry)
{
    if (r.y1 < r.y0) return;
    const int a0 = (r.x0 + 3) & ~3;        // first aligned float index
    const int a1 = (r.x1 + 1) & ~3;        // exclusive aligned end
    const int nvec = (a1 - a0) >> 2;       // float4 interior count
    const float4 f4 = make_float4(fill, fill, fill, fill);

    const int wl = r.x0 + qx;              // left-edge scalar (qx < 3)
    const bool do_l = (qx < 3) && (wl < a0);
    const int wr = a1 + (qx - 3);          // right-edge scalar (qx in [3,6))
    const bool do_r = (qx >= 3) && (qx < 6) && (wr <= r.x1);

    float* const base = out + (size_t)r.b * Hdim * Wdim + a0;
    for (int h = r.y0 + ry; h <= r.y1; h += 4) {
        float* const row = base + (size_t)h * Wdim;
        if (do_l) row[wl - a0] = fill;
        if (do_r) row[wr - a0] = fill;
        float4* const rowv = reinterpret_cast<float4*>(row);
        for (int q = qx; q < nvec; q += 64)
            rowv[q] = f4;
    }
}

__global__ void __launch_bounds__(NT, 4) fused_cutout_kernel(
    const float4* __restrict__ x, float4* __restrict__ out,
    const int* __restrict__ xs, const int* __restrict__ ys,
    const int* __restrict__ xs_w_raw, const int* __restrict__ ys_h_raw,
    const float* __restrict__ act_rand)
{
    // Read epoch before any block could possibly bump it (bump requires all
    // GRID tickets; ours comes later).
    const int epoch0 = *(volatile int*)&g_epoch;

    // ---- hoist fill geometry (mean-independent): block i owns hole i and,
    //      for i < 48, hole 592+i. Nothing but stores remain after the spin.
    const Rect r0 = load_rect(blockIdx.x, xs, ys, xs_w_raw, ys_h_raw, act_rand);
    const Rect r1 = load_rect(blockIdx.x + GRID, xs, ys, xs_w_raw, ys_h_raw,
                              act_rand);

    // ---- phase 1 (R11 exact): 6 iters x 8 batched + 7 batched + tail ----
    const int tg = blockIdx.x * NT + threadIdx.x;
    float s = 0.0f;
    #pragma unroll 1
    for (int k = 0; k < 6; ++k) {
        const long long b0 = (long long)k * (8 * (long long)TOTT) + tg;
        float4 v[8];
        #pragma unroll
        for (int j = 0; j < 8; ++j)
            v[j] = x[b0 + (long long)j * TOTT];
        #pragma unroll
        for (int j = 0; j < 8; ++j) {
            s += (v[j].x + v[j].y) + (v[j].z + v[j].w);
            out[b0 + (long long)j * TOTT] = v[j];
        }
    }
    {
        const long long b0 = 48LL * TOTT + tg;
        float4 v[7];
        #pragma unroll
        for (int j = 0; j < 7; ++j)
            v[j] = x[b0 + (long long)j * TOTT];
        #pragma unroll
        for (int j = 0; j < 7; ++j) {
            s += (v[j].x + v[j].y) + (v[j].z + v[j].w);
            out[b0 + (long long)j * TOTT] = v[j];
        }
    }
    {
        const long long i = 55LL * TOTT + tg;
        if (i < N4) {
            float4 v = x[i];
            s += (v.x + v.y) + (v.z + v.w);
            out[i] = v;
        }
    }

    #pragma unroll
    for (int o = 16; o > 0; o >>= 1)
        s += __shfl_down_sync(0xFFFFFFFFu, s, o);
    __shared__ float ws[8];
    const int lane = threadIdx.x & 31, warp = threadIdx.x >> 5;
    if (lane == 0) ws[warp] = s;
    __syncthreads();
    __shared__ int is_last;
    if (threadIdx.x == 0) {
        float v = ws[0];
        #pragma unroll
        for (int k = 1; k < 8; ++k) v += ws[k];
        g_partials[blockIdx.x] = v;
        __threadfence();
        int ticket = atomicAdd(&g_count, 1);
        is_last = (ticket == GRID - 1);
    }
    __syncthreads();

    if (is_last) {
        // fixed-order float reduction of GRID partials (deterministic)
        float s2 = 0.0f;
        for (int k = threadIdx.x; k < GRID; k += NT)
            s2 += g_partials[k];
        #pragma unroll
        for (int o = 16; o > 0; o >>= 1)
            s2 += __shfl_down_sync(0xFFFFFFFFu, s2, o);
        __shared__ float wf[8];
        if (lane == 0) wf[warp] = s2;
        __syncthreads();
        if (threadIdx.x == 0) {
            float t = wf[0];
            #pragma unroll
            for (int k = 1; k < 8; ++k) t += wf[k];
            g_mean = t * (1.0f / (float)N_TOTAL);
            g_count = 0;                   // reset for next replay
            __threadfence();
            *(volatile int*)&g_epoch = epoch0 + 1;   // release
        }
    }

    // Blocks with no active hole exit without spinning.
    if (r0.y1 < r0.y0 && r1.y1 < r1.y0) return;

    // ---- grid-wide sync: thread 0 spins, block follows ----
    if (threadIdx.x == 0) {
        while (*(volatile int*)&g_epoch == epoch0)
            __nanosleep(32);
    }
    __syncthreads();
    __threadfence();                       // acquire
    const float fill = *(volatile float*)&g_mean;

    // ---- phase 2: stores only ----
    const int qx = threadIdx.x & 63;       // quad lane
    const int ry = threadIdx.x >> 6;       // row lane (0..3)
    fill_rect(r0, fill, (float*)out, qx, ry);
    fill_rect(r1, fill, (float*)out, qx, ry);
}

extern "C" void kernel_launch(void* const* d_in, const int* in_sizes, int n_in,
                              void* d_out, int out_size) {
    const float* x        = (const float*)d_in[0];
    const int*   xs       = (const int*)d_in[1];
    const int*   ys       = (const int*)d_in[2];
    const int*   xs_w_raw = (const int*)d_in[3];
    const int*   ys_h_raw = (const int*)d_in[4];
    const float* act_rand = (const float*)d_in[5];
    float* out = (float*)d_out;

    fused_cutout_kernel<<<GRID, NT>>>((const float4*)x, (float4*)out,
                                      xs, ys, xs_w_raw, ys_h_raw, act_rand);
}

// round 16
// speedup vs baseline: 1.0117x; 1.0089x over previous
#include <cuda_runtime.h>
#include <cstdint>

#define Bsz 128
#define Hdim 256
#define Wdim 1024
#define N_HOLES 5
#define PROB 1.0f
#define HOLE_MINW (Wdim / 10)              // 102
#define HOLE_MINH (Hdim / 10)              // 25
#define N_TOTAL ((long long)Bsz * Hdim * Wdim)   // 33,554,432 floats
#define NHOLE_T (Bsz * N_HOLES)            // 640

#define GRID 592                           // 148 SMs * 4 -> perfectly balanced
#define NT 256
#define TOTT (GRID * NT)                   // 151,552 threads (f4 stride)
#define N4 (N_TOTAL / 4)                   // 8,388,608 float4 (img = 2^16 f4)
#define NSLOT 56                           // 6*8 + 7 + 1 access slots/thread

__device__ float g_partials[GRID];
__device__ float g_mean;
__device__ int   g_count = 0;              // last block resets -> replay-safe
__device__ int   g_epoch = 0;              // monotonic: bumps once per launch

__global__ void __launch_bounds__(NT, 4) fused_cutout_kernel(
    const float4* __restrict__ x, float4* __restrict__ out,
    const int* __restrict__ xs, const int* __restrict__ ys,
    const int* __restrict__ xs_w_raw, const int* __restrict__ ys_h_raw,
    const float* __restrict__ act_rand)
{
    // Read epoch before any block could possibly bump it (bump requires all
    // GRID tickets; ours comes later).
    const int epoch0 = *(volatile int*)&g_epoch;

    // ---- setup: all 640 clamped hole rects -> smem (reused by fill) ----
    __shared__ int4 srect[NHOLE_T];        // 10 KB
    for (int t = threadIdx.x; t < NHOLE_T; t += NT) {
        const int hw_ = xs_w_raw[t] + HOLE_MINW;
        const int hh_ = ys_h_raw[t] + HOLE_MINH;
        const int cx = xs[t], cy = ys[t];
        int4 r;
        r.x = min(max(cx - hw_ / 2, 0), Wdim - 2);
        r.y = min(max(cx + hw_ / 2, 1), Wdim - 1);
        r.z = min(max(cy - hh_ / 2, 0), Hdim - 2);
        r.w = min(max(cy + hh_ / 2, 1), Hdim - 1);
        if (!(act_rand[t] < PROB)) r.x = 1 << 30;   // inactive sentinel
        srect[t] = r;
    }
    __syncthreads();

    // ---- per-warp 64-bit skip mask over the 56 access slots ----
    // slot m touches float4 index idx = warpbase + m*TOTT; warp covers
    // 32 consecutive f4 = 128 floats in one row (img=2^16 f4, row=2^8 f4).
    const int lane = threadIdx.x & 31;
    const int wbase = blockIdx.x * NT + (threadIdx.x & ~31);
    uint64_t skipmask;
    {
        bool sa = false, sb = false;
        #pragma unroll
        for (int half = 0; half < 2; ++half) {
            const int m = lane + half * 32;
            bool sk = false;
            const long long idx = (long long)wbase + (long long)m * TOTT;
            if (m < NSLOT && idx < N4) {
                const int b  = (int)(idx >> 16);
                const int px = (int)(idx & 65535);
                const int h  = px >> 8;
                const int w0 = (px & 255) * 4;
                const int w1 = w0 + 127;
                const int hb = b * N_HOLES;
                #pragma unroll
                for (int n = 0; n < N_HOLES; ++n) {
                    int4 r = srect[hb + n];
                    sk |= (h >= r.z) & (h <= r.w) & (w0 >= r.x) & (w1 <= r.y);
                }
            }
            if (half == 0) sa = sk; else sb = sk;
        }
        uint32_t mlo = __ballot_sync(0xFFFFFFFFu, sa);
        uint32_t mhi = __ballot_sync(0xFFFFFFFFu, sb);
        skipmask = (uint64_t)mlo | ((uint64_t)mhi << 32);
    }

    // ---- phase 1 (R11 base + masked stores) ----
    const int tg = blockIdx.x * NT + threadIdx.x;
    float s = 0.0f;
    #pragma unroll 1
    for (int k = 0; k < 6; ++k) {
        const long long b0 = (long long)k * (8 * (long long)TOTT) + tg;
        const unsigned mk = (unsigned)(skipmask >> (k * 8)) & 255u;
        float4 v[8];
        #pragma unroll
        for (int j = 0; j < 8; ++j)
            v[j] = x[b0 + (long long)j * TOTT];
        #pragma unroll
        for (int j = 0; j < 8; ++j) {
            s += (v[j].x + v[j].y) + (v[j].z + v[j].w);
            if (!(mk & (1u << j)))
                out[b0 + (long long)j * TOTT] = v[j];
        }
    }
    {
        const long long b0 = 48LL * TOTT + tg;
        const unsigned mk = (unsigned)(skipmask >> 48) & 127u;
        float4 v[7];
        #pragma unroll
        for (int j = 0; j < 7; ++j)
            v[j] = x[b0 + (long long)j * TOTT];
        #pragma unroll
        for (int j = 0; j < 7; ++j) {
            s += (v[j].x + v[j].y) + (v[j].z + v[j].w);
            if (!(mk & (1u << j)))
                out[b0 + (long long)j * TOTT] = v[j];
        }
    }
    {
        const long long i = 55LL * TOTT + tg;
        if (i < N4) {
            float4 v = x[i];
            s += (v.x + v.y) + (v.z + v.w);
            if (!((skipmask >> 55) & 1ull))
                out[i] = v;
        }
    }

    #pragma unroll
    for (int o = 16; o > 0; o >>= 1)
        s += __shfl_down_sync(0xFFFFFFFFu, s, o);
    __shared__ float ws[8];
    const int warp = threadIdx.x >> 5;
    if (lane == 0) ws[warp] = s;
    __syncthreads();
    __shared__ int is_last;
    if (threadIdx.x == 0) {
        float v = ws[0];
        #pragma unroll
        for (int k = 1; k < 8; ++k) v += ws[k];
        g_partials[blockIdx.x] = v;
        __threadfence();
        int ticket = atomicAdd(&g_count, 1);
        is_last = (ticket == GRID - 1);
    }
    __syncthreads();

    if (is_last) {
        // fixed-order float reduction of GRID partials (deterministic)
        float s2 = 0.0f;
        for (int k = threadIdx.x; k < GRID; k += NT)
            s2 += g_partials[k];
        #pragma unroll
        for (int o = 16; o > 0; o >>= 1)
            s2 += __shfl_down_sync(0xFFFFFFFFu, s2, o);
        __shared__ float wf[8];
        if (lane == 0) wf[warp] = s2;
        __syncthreads();
        if (threadIdx.x == 0) {
            float t = wf[0];
            #pragma unroll
            for (int k = 1; k < 8; ++k) t += wf[k];
            g_mean = t * (1.0f / (float)N_TOTAL);
            g_count = 0;                   // reset for next replay
            __threadfence();
            *(volatile int*)&g_epoch = epoch0 + 1;   // release
        }
    }

    // ---- grid-wide sync: thread 0 spins, block follows ----
    if (threadIdx.x == 0) {
        while (*(volatile int*)&g_epoch == epoch0)
            __nanosleep(32);
    }
    __syncthreads();
    __threadfence();                       // acquire
    const float fill = *(volatile float*)&g_mean;
    const float4 f4 = make_float4(fill, fill, fill, fill);

    // ---- phase 2: block i fills hole i and (i < 48) hole i+GRID ----
    const int qx = threadIdx.x & 63;       // quad lane
    const int ry = threadIdx.x >> 6;       // row lane (0..3)

    #pragma unroll
    for (int pass = 0; pass < 2; ++pass) {
        const int hole = blockIdx.x + pass * GRID;
        if (hole >= NHOLE_T) break;
        const int4 r = srect[hole];
        if (r.x >= Wdim) continue;         // inactive sentinel

        const int b = hole / N_HOLES;
        const int a0 = (r.x + 3) & ~3;     // first aligned float index
        const int a1 = (r.y + 1) & ~3;     // exclusive aligned end
        const int nvec = (a1 - a0) >> 2;   // float4 interior count

        const int wl = r.x + qx;           // left-edge scalar (qx < 3)
        const bool do_l = (qx < 3) && (wl < a0);
        const int wr = a1 + (qx - 3);      // right-edge scalar (qx in [3,6))
        const bool do_r = (qx >= 3) && (qx < 6) && (wr <= r.y);

        float* const base = (float*)out + (size_t)b * Hdim * Wdim + a0;
        for (int h = r.z + ry; h <= r.w; h += 4) {
            float* const row = base + (size_t)h * Wdim;
            if (do_l) row[wl - a0] = fill;
            if (do_r) row[wr - a0] = fill;
            float4* const rowv = reinterpret_cast<float4*>(row);
            for (int q = qx; q < nvec; q += 64)
                rowv[q] = f4;
        }
    }
}

extern "C" void kernel_launch(void* const* d_in, const int* in_sizes, int n_in,
                              void* d_out, int out_size) {
    const float* x        = (const float*)d_in[0];
    const int*   xs       = (const int*)d_in[1];
    const int*   ys       = (const int*)d_in[2];
    const int*   xs_w_raw = (const int*)d_in[3];
    const int*   ys_h_raw = (const int*)d_in[4];
    const float* act_rand = (const float*)d_in[5];
    float* out = (float*)d_out;

    fused_cutout_kernel<<<GRID, NT>>>((const float4*)x, (float4*)out,
                                      xs, ys, xs_w_raw, ys_h_raw, act_rand);
}